// round 1
// baseline (speedup 1.0000x reference)
#include <cuda_runtime.h>
#include <math.h>

#define T 1024
#define H 1024
#define FF 2048
#define E 8
#define KSEL 2
#define NSLOT (T * KSEL)   // 2048

// ---------------- scratch (device globals: allocation-free) ----------------
__device__ int   g_count[E];
__device__ int   g_offset[E];
__device__ int   g_tok[NSLOT];
__device__ float g_scale[NSLOT];
__device__ float g_act[(size_t)NSLOT * FF];   // 16.8 MB activation scratch

// ---------------- routing: histogram + prefix + compact ----------------
__global__ void route_kernel(const int* __restrict__ sel,
                             const float* __restrict__ scales) {
    __shared__ int s_cnt[E], s_off[E], s_cur[E];
    int tid = threadIdx.x;
    if (tid < E) { s_cnt[tid] = 0; s_cur[tid] = 0; }
    __syncthreads();
    for (int i = tid; i < NSLOT; i += blockDim.x)
        atomicAdd(&s_cnt[sel[i]], 1);
    __syncthreads();
    if (tid == 0) {
        int acc = 0;
        for (int e = 0; e < E; e++) { s_off[e] = acc; acc += s_cnt[e]; }
    }
    __syncthreads();
    if (tid < E) { g_count[tid] = s_cnt[tid]; g_offset[tid] = s_off[tid]; }
    for (int i = tid; i < NSLOT; i += blockDim.x) {
        int e = sel[i];
        int pos = s_off[e] + atomicAdd(&s_cur[e], 1);
        g_tok[pos]   = i / KSEL;
        g_scale[pos] = scales[i];
    }
}

// ---------------- GEMM1: act = silu(X*W1g + b1g) * (X*W1l + b1l) ----------
// Tile 64(M) x 64(N over F), K-step 16. Computes gate AND lin tiles together.
__global__ __launch_bounds__(256)
void gemm1_kernel(const float* __restrict__ hidden,
                  const float* __restrict__ w1,
                  const float* __restrict__ b1) {
    int e   = blockIdx.y;
    int cnt = g_count[e];
    int m0  = blockIdx.z * 64;
    if (m0 >= cnt) return;
    int off = g_offset[e];
    int n0  = blockIdx.x * 64;

    __shared__ float As[16][68];
    __shared__ float Bg[16][68];
    __shared__ float Bl[16][68];

    int tid = threadIdx.x;
    int tx = tid & 15, ty = tid >> 4;
    int lr = tid >> 2;          // load row 0..63
    int lk = (tid & 3) * 4;     // k offset 0,4,8,12

    int tokr = (m0 + lr < cnt) ? g_tok[off + m0 + lr] : -1;
    int tok_safe = (tokr >= 0) ? tokr : 0;
    const float* aptr  = hidden + (size_t)tok_safe * H + lk;
    const float* bgptr = w1 + ((size_t)e * 2 * FF + (n0 + lr)) * H + lk;
    const float* blptr = w1 + ((size_t)e * 2 * FF + FF + (n0 + lr)) * H + lk;

    float cg[4][4] = {}, cl[4][4] = {};

    for (int kt = 0; kt < H; kt += 16) {
        float4 av  = *(const float4*)(aptr  + kt);
        if (tokr < 0) av = make_float4(0.f, 0.f, 0.f, 0.f);
        float4 bgv = *(const float4*)(bgptr + kt);
        float4 blv = *(const float4*)(blptr + kt);

        __syncthreads();
        As[lk+0][lr] = av.x;  As[lk+1][lr] = av.y;
        As[lk+2][lr] = av.z;  As[lk+3][lr] = av.w;
        Bg[lk+0][lr] = bgv.x; Bg[lk+1][lr] = bgv.y;
        Bg[lk+2][lr] = bgv.z; Bg[lk+3][lr] = bgv.w;
        Bl[lk+0][lr] = blv.x; Bl[lk+1][lr] = blv.y;
        Bl[lk+2][lr] = blv.z; Bl[lk+3][lr] = blv.w;
        __syncthreads();

        #pragma unroll
        for (int kk = 0; kk < 16; kk++) {
            float a[4], g[4], l[4];
            *(float4*)a = *(const float4*)&As[kk][ty * 4];
            *(float4*)g = *(const float4*)&Bg[kk][tx * 4];
            *(float4*)l = *(const float4*)&Bl[kk][tx * 4];
            #pragma unroll
            for (int i = 0; i < 4; i++)
                #pragma unroll
                for (int j = 0; j < 4; j++) {
                    cg[i][j] = fmaf(a[i], g[j], cg[i][j]);
                    cl[i][j] = fmaf(a[i], l[j], cl[i][j]);
                }
        }
    }

    // epilogue: bias + silu(gate)*lin, vectorized store
    const float* b1g = b1 + (size_t)e * 2 * FF;
    #pragma unroll
    for (int i = 0; i < 4; i++) {
        int m = m0 + ty * 4 + i;
        if (m >= cnt) continue;
        int row = off + m;
        float4 o;
        float* op = (float*)&o;
        #pragma unroll
        for (int j = 0; j < 4; j++) {
            int n = n0 + tx * 4 + j;
            float gate = cg[i][j] + b1g[n];
            float lin  = cl[i][j] + b1g[FF + n];
            float s = 1.0f / (1.0f + expf(-gate));
            op[j] = gate * s * lin;
        }
        *(float4*)&g_act[(size_t)row * FF + n0 + tx * 4] = o;
    }
}

// ---------------- GEMM2: y = act * W2^T + b2, scatter-add scaled ----------
__global__ __launch_bounds__(256)
void gemm2_kernel(const float* __restrict__ w2,
                  const float* __restrict__ b2,
                  float* __restrict__ out) {
    int e   = blockIdx.y;
    int cnt = g_count[e];
    int m0  = blockIdx.z * 64;
    if (m0 >= cnt) return;
    int off = g_offset[e];
    int n0  = blockIdx.x * 64;   // over H

    __shared__ float As[16][68];
    __shared__ float Bs[16][68];

    int tid = threadIdx.x;
    int tx = tid & 15, ty = tid >> 4;
    int lr = tid >> 2;
    int lk = (tid & 3) * 4;

    int mrow_ok = (m0 + lr < cnt);
    int arow = off + (mrow_ok ? m0 + lr : 0);
    const float* aptr = g_act + (size_t)arow * FF + lk;
    const float* bptr = w2 + ((size_t)e * H + (n0 + lr)) * FF + lk;

    float c[4][4] = {};

    for (int kt = 0; kt < FF; kt += 16) {
        float4 av = *(const float4*)(aptr + kt);
        if (!mrow_ok) av = make_float4(0.f, 0.f, 0.f, 0.f);
        float4 bv = *(const float4*)(bptr + kt);

        __syncthreads();
        As[lk+0][lr] = av.x; As[lk+1][lr] = av.y;
        As[lk+2][lr] = av.z; As[lk+3][lr] = av.w;
        Bs[lk+0][lr] = bv.x; Bs[lk+1][lr] = bv.y;
        Bs[lk+2][lr] = bv.z; Bs[lk+3][lr] = bv.w;
        __syncthreads();

        #pragma unroll
        for (int kk = 0; kk < 16; kk++) {
            float a[4], b[4];
            *(float4*)a = *(const float4*)&As[kk][ty * 4];
            *(float4*)b = *(const float4*)&Bs[kk][tx * 4];
            #pragma unroll
            for (int i = 0; i < 4; i++)
                #pragma unroll
                for (int j = 0; j < 4; j++)
                    c[i][j] = fmaf(a[i], b[j], c[i][j]);
        }
    }

    const float* b2e = b2 + (size_t)e * H;
    #pragma unroll
    for (int i = 0; i < 4; i++) {
        int m = m0 + ty * 4 + i;
        if (m >= cnt) continue;
        int tok   = g_tok[off + m];
        float sc  = g_scale[off + m];
        #pragma unroll
        for (int j = 0; j < 4; j++) {
            int n = n0 + tx * 4 + j;
            atomicAdd(&out[(size_t)tok * H + n], sc * (c[i][j] + b2e[n]));
        }
    }
}

// ---------------- launch ----------------
extern "C" void kernel_launch(void* const* d_in, const int* in_sizes, int n_in,
                              void* d_out, int out_size) {
    const float* hidden = (const float*)d_in[0];
    const int*   sel    = (const int*)d_in[1];
    const float* scales = (const float*)d_in[2];
    const float* w1     = (const float*)d_in[3];
    const float* b1     = (const float*)d_in[4];
    const float* w2     = (const float*)d_in[5];
    const float* b2     = (const float*)d_in[6];
    float* out = (float*)d_out;

    cudaMemsetAsync(d_out, 0, (size_t)T * H * sizeof(float), 0);
    route_kernel<<<1, 256>>>(sel, scales);

    dim3 g1(FF / 64, E, NSLOT / 64);   // 32 x 8 x 32
    gemm1_kernel<<<g1, 256>>>(hidden, w1, b1);

    dim3 g2(H / 64, E, NSLOT / 64);    // 16 x 8 x 32
    gemm2_kernel<<<g2, 256>>>(w2, b2, out);
}

// round 3
// speedup vs baseline: 1.7122x; 1.7122x over previous
#include <cuda_runtime.h>
#include <cuda_bf16.h>
#include <math.h>
#include <stdint.h>

#define T 1024
#define H 1024
#define FF 2048
#define E 8
#define KSEL 2
#define NSLOT (T * KSEL)   // 2048

// ---------------- scratch (device globals: allocation-free) ----------------
__device__ int   g_count[E];
__device__ int   g_offset[E];
__device__ int   g_tok[NSLOT];
__device__ float g_scale[NSLOT];
__device__ float g_act[(size_t)NSLOT * FF];   // 16.8 MB activation scratch

// ---------------- helpers ----------------
__device__ __forceinline__ uint32_t s2u(const void* p) {
    return (uint32_t)__cvta_generic_to_shared(p);
}

__device__ __forceinline__ void ldsm4(uint32_t (&r)[4], uint32_t addr) {
    asm volatile("ldmatrix.sync.aligned.m8n8.x4.shared.b16 {%0,%1,%2,%3}, [%4];"
                 : "=r"(r[0]), "=r"(r[1]), "=r"(r[2]), "=r"(r[3]) : "r"(addr));
}
__device__ __forceinline__ void ldsm2(uint32_t (&r)[2], uint32_t addr) {
    asm volatile("ldmatrix.sync.aligned.m8n8.x2.shared.b16 {%0,%1}, [%2];"
                 : "=r"(r[0]), "=r"(r[1]) : "r"(addr));
}
__device__ __forceinline__ void mma16816(float (&c)[4], const uint32_t (&a)[4],
                                         const uint32_t (&b)[2]) {
    asm volatile(
        "mma.sync.aligned.m16n8k16.row.col.f32.bf16.bf16.f32 "
        "{%0,%1,%2,%3},{%4,%5,%6,%7},{%8,%9},{%0,%1,%2,%3};"
        : "+f"(c[0]), "+f"(c[1]), "+f"(c[2]), "+f"(c[3])
        : "r"(a[0]), "r"(a[1]), "r"(a[2]), "r"(a[3]), "r"(b[0]), "r"(b[1]));
}

// split fp32 pair -> packed bf16x2 (hi) + packed bf16x2 (lo residual)
__device__ __forceinline__ void split2(float x0, float x1, uint32_t& h, uint32_t& l) {
    __nv_bfloat16 h0 = __float2bfloat16(x0);
    __nv_bfloat16 h1 = __float2bfloat16(x1);
    __nv_bfloat16 l0 = __float2bfloat16(x0 - __bfloat162float(h0));
    __nv_bfloat16 l1 = __float2bfloat16(x1 - __bfloat162float(h1));
    h = (uint32_t)__bfloat16_as_ushort(h0) | ((uint32_t)__bfloat16_as_ushort(h1) << 16);
    l = (uint32_t)__bfloat16_as_ushort(l0) | ((uint32_t)__bfloat16_as_ushort(l1) << 16);
}

// smem row stride: 32 bf16 = 64B data + 16B pad = 80B (conflict-free ldmatrix)
#define LDS_ROW 80

// ---------------- routing: histogram + prefix + compact ----------------
__global__ void route_kernel(const int* __restrict__ sel,
                             const float* __restrict__ scales) {
    __shared__ int s_cnt[E], s_off[E], s_cur[E];
    int tid = threadIdx.x;
    if (tid < E) { s_cnt[tid] = 0; s_cur[tid] = 0; }
    __syncthreads();
    for (int i = tid; i < NSLOT; i += blockDim.x)
        atomicAdd(&s_cnt[sel[i]], 1);
    __syncthreads();
    if (tid == 0) {
        int acc = 0;
        for (int e = 0; e < E; e++) { s_off[e] = acc; acc += s_cnt[e]; }
    }
    __syncthreads();
    if (tid < E) { g_count[tid] = s_cnt[tid]; g_offset[tid] = s_off[tid]; }
    for (int i = tid; i < NSLOT; i += blockDim.x) {
        int e = sel[i];
        int pos = s_off[e] + atomicAdd(&s_cur[e], 1);
        g_tok[pos]   = i / KSEL;
        g_scale[pos] = scales[i];
    }
}

// ---------------- GEMM1: act = silu(X*W1g+b) * (X*W1l+b) -------------------
// CTA tile: M=128, Ngate=64, Nlin=64, Kchunk=32, bf16 split-2, 3 products.
#define G1_AHI 0
#define G1_ALO (128 * LDS_ROW)
#define G1_GHI (2 * 128 * LDS_ROW)
#define G1_GLO (G1_GHI + 64 * LDS_ROW)
#define G1_LHI (G1_GHI + 2 * 64 * LDS_ROW)
#define G1_LLO (G1_GHI + 3 * 64 * LDS_ROW)
#define G1_BUF (G1_GHI + 4 * 64 * LDS_ROW)   // 40960

__global__ __launch_bounds__(256, 1)
void gemm1_kernel(const float* __restrict__ hidden,
                  const float* __restrict__ w1,
                  const float* __restrict__ b1) {
    const int e   = blockIdx.y;
    const int cnt = g_count[e];
    const int m0  = blockIdx.z * 128;
    if (m0 >= cnt) return;
    const int n0  = blockIdx.x * 64;
    const int off = g_offset[e];

    extern __shared__ char sm[];
    __shared__ float s_bg[64], s_bl[64];

    const int tid = threadIdx.x, lane = tid & 31, wid = tid >> 5;
    const int wm = wid & 1, wn = wid >> 1;

    if (tid < 64)       s_bg[tid]      = b1[(size_t)e * 2 * FF + n0 + tid];
    else if (tid < 128) s_bl[tid - 64] = b1[(size_t)e * 2 * FF + FF + n0 + tid - 64];

    // gmem load mapping
    const int arow = tid >> 1, acb = (tid & 1) * 16;       // A: 128 rows x 32 cols
    const int mrow = m0 + arow;
    const int slot = off + (mrow < cnt ? mrow : cnt - 1);
    const float* pA  = hidden + (size_t)g_tok[slot] * H + acb;
    const uint32_t aoff = (uint32_t)arow * LDS_ROW + acb * 2;

    const int brow = tid >> 2, bcb = (tid & 3) * 8;        // B: 64 rows x 32 cols
    const float* pBg = w1 + ((size_t)e * 2 * FF + n0 + brow) * H + bcb;
    const float* pBl = pBg + (size_t)FF * H;
    const uint32_t boff = (uint32_t)brow * LDS_ROW + bcb * 2;

    float cg[4][2][4] = {}, cl[4][2][4] = {};
    float ra[16], rg[8], rl[8];

    // ldmatrix base addresses (per-thread)
    const uint32_t smb = s2u(sm);
    const uint32_t la = (lane & 15) * LDS_ROW + (lane >> 4) * 16 + wm * (64 * LDS_ROW);
    const uint32_t lb = (lane & 7) * LDS_ROW + ((lane >> 3) & 1) * 16 + wn * (16 * LDS_ROW);

    // prologue: load + store chunk 0
#pragma unroll
    for (int j = 0; j < 4; j++) *(float4*)&ra[j * 4] = *(const float4*)(pA + j * 4);
#pragma unroll
    for (int j = 0; j < 2; j++) *(float4*)&rg[j * 4] = *(const float4*)(pBg + j * 4);
#pragma unroll
    for (int j = 0; j < 2; j++) *(float4*)&rl[j * 4] = *(const float4*)(pBl + j * 4);

    const int NK = H / 32;
    for (int kt = 0; kt < NK; kt++) {
        // store regs (chunk kt) into buffer kt&1
        {
            char* bb = sm + (kt & 1) * G1_BUF;
            uint32_t h[8], l[8];
#pragma unroll
            for (int j = 0; j < 8; j++) split2(ra[2 * j], ra[2 * j + 1], h[j], l[j]);
            *(uint4*)(bb + G1_AHI + aoff)      = make_uint4(h[0], h[1], h[2], h[3]);
            *(uint4*)(bb + G1_AHI + aoff + 16) = make_uint4(h[4], h[5], h[6], h[7]);
            *(uint4*)(bb + G1_ALO + aoff)      = make_uint4(l[0], l[1], l[2], l[3]);
            *(uint4*)(bb + G1_ALO + aoff + 16) = make_uint4(l[4], l[5], l[6], l[7]);
#pragma unroll
            for (int j = 0; j < 4; j++) split2(rg[2 * j], rg[2 * j + 1], h[j], l[j]);
            *(uint4*)(bb + G1_GHI + boff) = make_uint4(h[0], h[1], h[2], h[3]);
            *(uint4*)(bb + G1_GLO + boff) = make_uint4(l[0], l[1], l[2], l[3]);
#pragma unroll
            for (int j = 0; j < 4; j++) split2(rl[2 * j], rl[2 * j + 1], h[j], l[j]);
            *(uint4*)(bb + G1_LHI + boff) = make_uint4(h[0], h[1], h[2], h[3]);
            *(uint4*)(bb + G1_LLO + boff) = make_uint4(l[0], l[1], l[2], l[3]);
        }
        __syncthreads();

        // prefetch chunk kt+1
        if (kt + 1 < NK) {
            const int ko = (kt + 1) * 32;
#pragma unroll
            for (int j = 0; j < 4; j++) *(float4*)&ra[j * 4] = *(const float4*)(pA + ko + j * 4);
#pragma unroll
            for (int j = 0; j < 2; j++) *(float4*)&rg[j * 4] = *(const float4*)(pBg + ko + j * 4);
#pragma unroll
            for (int j = 0; j < 2; j++) *(float4*)&rl[j * 4] = *(const float4*)(pBl + ko + j * 4);
        }

        // compute on buffer kt&1
        {
            const uint32_t bb = smb + (kt & 1) * G1_BUF;
#pragma unroll
            for (int kk = 0; kk < 2; kk++) {
                uint32_t ah[4][4], al[4][4];
#pragma unroll
                for (int i = 0; i < 4; i++) {
                    ldsm4(ah[i], bb + G1_AHI + la + i * (16 * LDS_ROW) + kk * 32);
                    ldsm4(al[i], bb + G1_ALO + la + i * (16 * LDS_ROW) + kk * 32);
                }
                uint32_t bgh[2][2], bgl[2][2], blh[2][2], bll[2][2];
#pragma unroll
                for (int j = 0; j < 2; j++) {
                    ldsm2(bgh[j], bb + G1_GHI + lb + j * (8 * LDS_ROW) + kk * 32);
                    ldsm2(bgl[j], bb + G1_GLO + lb + j * (8 * LDS_ROW) + kk * 32);
                    ldsm2(blh[j], bb + G1_LHI + lb + j * (8 * LDS_ROW) + kk * 32);
                    ldsm2(bll[j], bb + G1_LLO + lb + j * (8 * LDS_ROW) + kk * 32);
                }
#pragma unroll
                for (int i = 0; i < 4; i++)
#pragma unroll
                    for (int j = 0; j < 2; j++) {
                        mma16816(cg[i][j], ah[i], bgh[j]);
                        mma16816(cg[i][j], ah[i], bgl[j]);
                        mma16816(cg[i][j], al[i], bgh[j]);
                        mma16816(cl[i][j], ah[i], blh[j]);
                        mma16816(cl[i][j], ah[i], bll[j]);
                        mma16816(cl[i][j], al[i], blh[j]);
                    }
            }
        }
        __syncthreads();
    }

    // epilogue: bias + silu(gate)*lin, float2 stores to g_act
#pragma unroll
    for (int i = 0; i < 4; i++)
#pragma unroll
        for (int j = 0; j < 2; j++) {
            const int c = wn * 16 + j * 8 + (lane & 3) * 2;
            const float bg0 = s_bg[c], bg1 = s_bg[c + 1];
            const float bl0 = s_bl[c], bl1 = s_bl[c + 1];
#pragma unroll
            for (int rr = 0; rr < 2; rr++) {
                const int m = wm * 64 + i * 16 + (lane >> 2) + rr * 8 + m0;
                if (m >= cnt) continue;
                const float g0 = cg[i][j][rr * 2 + 0] + bg0;
                const float g1 = cg[i][j][rr * 2 + 1] + bg1;
                const float v0 = cl[i][j][rr * 2 + 0] + bl0;
                const float v1 = cl[i][j][rr * 2 + 1] + bl1;
                float2 o;
                o.x = g0 * v0 / (1.0f + __expf(-g0));
                o.y = g1 * v1 / (1.0f + __expf(-g1));
                *(float2*)&g_act[(size_t)(off + m) * FF + n0 + c] = o;
            }
        }
}

// ---------------- GEMM2: out += scale*(act*W2^T + b2) ----------------------
// CTA tile: M=128, N=64 (over H), K=FF, Kchunk=32.
#define G2_AHI 0
#define G2_ALO (128 * LDS_ROW)
#define G2_BHI (2 * 128 * LDS_ROW)
#define G2_BLO (G2_BHI + 64 * LDS_ROW)
#define G2_BUF (G2_BHI + 2 * 64 * LDS_ROW)   // 30720

__global__ __launch_bounds__(256, 1)
void gemm2_kernel(const float* __restrict__ w2,
                  const float* __restrict__ b2,
                  float* __restrict__ out) {
    const int e   = blockIdx.y;
    const int cnt = g_count[e];
    const int m0  = blockIdx.z * 128;
    if (m0 >= cnt) return;
    const int n0  = blockIdx.x * 64;
    const int off = g_offset[e];

    extern __shared__ char sm[];
    __shared__ float s_b2[64];

    const int tid = threadIdx.x, lane = tid & 31, wid = tid >> 5;
    const int wm = wid & 1, wn = wid >> 1;

    if (tid < 64) s_b2[tid] = b2[(size_t)e * H + n0 + tid];

    const int arow = tid >> 1, acb = (tid & 1) * 16;
    const int mrow = m0 + arow;
    const float* pA = g_act + (size_t)(off + (mrow < cnt ? mrow : cnt - 1)) * FF + acb;
    const uint32_t aoff = (uint32_t)arow * LDS_ROW + acb * 2;

    const int brow = tid >> 2, bcb = (tid & 3) * 8;
    const float* pB = w2 + ((size_t)e * H + n0 + brow) * FF + bcb;
    const uint32_t boff = (uint32_t)brow * LDS_ROW + bcb * 2;

    float c[4][2][4] = {};
    float ra[16], rb[8];

    const uint32_t smb = s2u(sm);
    const uint32_t la = (lane & 15) * LDS_ROW + (lane >> 4) * 16 + wm * (64 * LDS_ROW);
    const uint32_t lb = (lane & 7) * LDS_ROW + ((lane >> 3) & 1) * 16 + wn * (16 * LDS_ROW);

#pragma unroll
    for (int j = 0; j < 4; j++) *(float4*)&ra[j * 4] = *(const float4*)(pA + j * 4);
#pragma unroll
    for (int j = 0; j < 2; j++) *(float4*)&rb[j * 4] = *(const float4*)(pB + j * 4);

    const int NK = FF / 32;
    for (int kt = 0; kt < NK; kt++) {
        {
            char* bb = sm + (kt & 1) * G2_BUF;
            uint32_t h[8], l[8];
#pragma unroll
            for (int j = 0; j < 8; j++) split2(ra[2 * j], ra[2 * j + 1], h[j], l[j]);
            *(uint4*)(bb + G2_AHI + aoff)      = make_uint4(h[0], h[1], h[2], h[3]);
            *(uint4*)(bb + G2_AHI + aoff + 16) = make_uint4(h[4], h[5], h[6], h[7]);
            *(uint4*)(bb + G2_ALO + aoff)      = make_uint4(l[0], l[1], l[2], l[3]);
            *(uint4*)(bb + G2_ALO + aoff + 16) = make_uint4(l[4], l[5], l[6], l[7]);
#pragma unroll
            for (int j = 0; j < 4; j++) split2(rb[2 * j], rb[2 * j + 1], h[j], l[j]);
            *(uint4*)(bb + G2_BHI + boff) = make_uint4(h[0], h[1], h[2], h[3]);
            *(uint4*)(bb + G2_BLO + boff) = make_uint4(l[0], l[1], l[2], l[3]);
        }
        __syncthreads();

        if (kt + 1 < NK) {
            const int ko = (kt + 1) * 32;
#pragma unroll
            for (int j = 0; j < 4; j++) *(float4*)&ra[j * 4] = *(const float4*)(pA + ko + j * 4);
#pragma unroll
            for (int j = 0; j < 2; j++) *(float4*)&rb[j * 4] = *(const float4*)(pB + ko + j * 4);
        }

        {
            const uint32_t bb = smb + (kt & 1) * G2_BUF;
#pragma unroll
            for (int kk = 0; kk < 2; kk++) {
                uint32_t ah[4][4], al[4][4];
#pragma unroll
                for (int i = 0; i < 4; i++) {
                    ldsm4(ah[i], bb + G2_AHI + la + i * (16 * LDS_ROW) + kk * 32);
                    ldsm4(al[i], bb + G2_ALO + la + i * (16 * LDS_ROW) + kk * 32);
                }
                uint32_t bh[2][2], bl[2][2];
#pragma unroll
                for (int j = 0; j < 2; j++) {
                    ldsm2(bh[j], bb + G2_BHI + lb + j * (8 * LDS_ROW) + kk * 32);
                    ldsm2(bl[j], bb + G2_BLO + lb + j * (8 * LDS_ROW) + kk * 32);
                }
#pragma unroll
                for (int i = 0; i < 4; i++)
#pragma unroll
                    for (int j = 0; j < 2; j++) {
                        mma16816(c[i][j], ah[i], bh[j]);
                        mma16816(c[i][j], ah[i], bl[j]);
                        mma16816(c[i][j], al[i], bh[j]);
                    }
            }
        }
        __syncthreads();
    }

    // epilogue: scaled atomic scatter
#pragma unroll
    for (int i = 0; i < 4; i++)
#pragma unroll
        for (int rr = 0; rr < 2; rr++) {
            const int m = wm * 64 + i * 16 + (lane >> 2) + rr * 8 + m0;
            if (m >= cnt) continue;
            const int   tok = g_tok[off + m];
            const float sc  = g_scale[off + m];
#pragma unroll
            for (int j = 0; j < 2; j++) {
                const int cc = wn * 16 + j * 8 + (lane & 3) * 2;
                atomicAdd(&out[(size_t)tok * H + n0 + cc],
                          sc * (c[i][j][rr * 2 + 0] + s_b2[cc]));
                atomicAdd(&out[(size_t)tok * H + n0 + cc + 1],
                          sc * (c[i][j][rr * 2 + 1] + s_b2[cc + 1]));
            }
        }
}

// ---------------- launch ----------------
extern "C" void kernel_launch(void* const* d_in, const int* in_sizes, int n_in,
                              void* d_out, int out_size) {
    const float* hidden = (const float*)d_in[0];
    const int*   sel    = (const int*)d_in[1];
    const float* scales = (const float*)d_in[2];
    const float* w1     = (const float*)d_in[3];
    const float* b1     = (const float*)d_in[4];
    const float* w2     = (const float*)d_in[5];
    const float* b2     = (const float*)d_in[6];

    const int smem1 = 2 * G1_BUF;   // 81920
    const int smem2 = 2 * G2_BUF;   // 61440
    cudaFuncSetAttribute(gemm1_kernel, cudaFuncAttributeMaxDynamicSharedMemorySize, smem1);
    cudaFuncSetAttribute(gemm2_kernel, cudaFuncAttributeMaxDynamicSharedMemorySize, smem2);

    cudaMemsetAsync(d_out, 0, (size_t)T * H * sizeof(float), 0);
    route_kernel<<<1, 256>>>(sel, scales);

    dim3 g1(FF / 64, E, NSLOT / 128);   // 32 x 8 x 16
    gemm1_kernel<<<g1, 256, smem1>>>(hidden, w1, b1);

    dim3 g2(H / 64, E, NSLOT / 128);    // 16 x 8 x 16
    gemm2_kernel<<<g2, 256, smem2>>>(w2, b2, (float*)d_out);
}